// round 3
// baseline (speedup 1.0000x reference)
#include <cuda_runtime.h>
#include <cuda_bf16.h>
#include <cooperative_groups.h>
#include <math.h>

namespace cg = cooperative_groups;

#define S_SPK   2
#define BB      16
#define TT      300
#define CC      3000
#define NSTATES 400
#define NARCS   1200
#define DSTATES 3000
#define DARCS   60000
#define NPAIR   (S_SPK * BB)        // 32
#define CLUSTER 4
#define SLICE   (DSTATES / CLUSTER) // 750
#define FWD_THREADS 768
#define LN2 0.6931471805599453

// ---------------- device scratch (static globals, no allocation) ----------------
__device__ int   g_den_hist[DSTATES];
__device__ int   g_den_rowptr[DSTATES + 1];
__device__ int   g_den_cursor[DSTATES];
__device__ uint2 g_den_arcs[DARCS];

__device__ int   g_num_rowptr[NPAIR][NSTATES + 1];
__device__ uint2 g_num_arcs[NPAIR * NARCS];

__device__ float g_denZ[NPAIR];              // [s*BB + b]
__device__ float g_numZ[S_SPK][S_SPK][BB];   // [speaker s][graph g][b]

// ---------------- prep: counting sort of den arcs by dst ----------------
__global__ void k_zero_hist() {
    int i = blockIdx.x * blockDim.x + threadIdx.x;
    if (i < DSTATES) g_den_hist[i] = 0;
}

__global__ void k_den_hist(const int* __restrict__ dst) {
    int i = blockIdx.x * blockDim.x + threadIdx.x;
    if (i < DARCS) atomicAdd(&g_den_hist[dst[i]], 1);
}

// single-CTA exclusive scan over 3000 counts (3 elems/thread, 1024 threads)
__global__ void k_den_scan() {
    __shared__ int ssum[1024];
    int tid = threadIdx.x;
    int base = tid * 3;
    int a = 0, b = 0, c = 0;
    if (base     < DSTATES) a = g_den_hist[base];
    if (base + 1 < DSTATES) b = g_den_hist[base + 1];
    if (base + 2 < DSTATES) c = g_den_hist[base + 2];
    int local = a + b + c;
    ssum[tid] = local;
    __syncthreads();
    for (int off = 1; off < 1024; off <<= 1) {
        int v = (tid >= off) ? ssum[tid - off] : 0;
        __syncthreads();
        ssum[tid] += v;
        __syncthreads();
    }
    int excl = ssum[tid] - local;
    if (base < DSTATES)     { g_den_rowptr[base]     = excl;         g_den_cursor[base]     = excl; }
    if (base + 1 < DSTATES) { g_den_rowptr[base + 1] = excl + a;     g_den_cursor[base + 1] = excl + a; }
    if (base + 2 < DSTATES) { g_den_rowptr[base + 2] = excl + a + b; g_den_cursor[base + 2] = excl + a + b; }
    if (tid == 1023) g_den_rowptr[DSTATES] = ssum[1023];
}

__global__ void k_den_scatter(const int* __restrict__ src, const int* __restrict__ dst,
                              const int* __restrict__ lab, const float* __restrict__ w) {
    int i = blockIdx.x * blockDim.x + threadIdx.x;
    if (i < DARCS) {
        int d = dst[i];
        int pos = atomicAdd(&g_den_cursor[d], 1);
        g_den_arcs[pos] = make_uint2((unsigned)src[i] | ((unsigned)lab[i] << 16),
                                     __float_as_uint(expf(w[i])));
    }
}

// one CTA per (graph g, batch b): hist + scan + scatter entirely in smem
__global__ void __launch_bounds__(512, 1) k_num_prep(const int* __restrict__ src,
                                                     const int* __restrict__ dst,
                                                     const int* __restrict__ lab,
                                                     const float* __restrict__ w) {
    int gb = blockIdx.x;  // 0..31
    const int*   s_ = src + gb * NARCS;
    const int*   d_ = dst + gb * NARCS;
    const int*   l_ = lab + gb * NARCS;
    const float* w_ = w   + gb * NARCS;
    __shared__ int hist[512];
    __shared__ int scan[512];
    __shared__ int cursor[NSTATES];
    int tid = threadIdx.x;
    hist[tid] = 0;
    __syncthreads();
    for (int i = tid; i < NARCS; i += 512) atomicAdd(&hist[d_[i]], 1);
    __syncthreads();
    int local = hist[tid];
    scan[tid] = local;
    __syncthreads();
    for (int off = 1; off < 512; off <<= 1) {
        int v = (tid >= off) ? scan[tid - off] : 0;
        __syncthreads();
        scan[tid] += v;
        __syncthreads();
    }
    int excl = scan[tid] - local;
    if (tid < NSTATES) { g_num_rowptr[gb][tid] = excl; cursor[tid] = excl; }
    if (tid == NSTATES) g_num_rowptr[gb][NSTATES] = NARCS;
    __syncthreads();
    for (int i = tid; i < NARCS; i += 512) {
        int d = d_[i];
        int pos = atomicAdd(&cursor[d], 1);
        g_num_arcs[gb * NARCS + pos] =
            make_uint2((unsigned)s_[i] | ((unsigned)l_[i] << 16), __float_as_uint(expf(w_[i])));
    }
}

// ---------------- fused forward: den (clustered) + num (ranks 0,1) ----------------
// dynamic smem layout (floats):
//   pd  [2][DSTATES]   : den alpha, replicated, double-buffered
//   fr  [2][CC]        : exp(llh) frame, replicated, double-buffered
//   pn  [2][NSTATES]   : num alpha (ranks 0,1 only)
//   redd[24], redn[24] : block reduction scratch
//   bc  [2]            : broadcast (den max, num max)
#define SM_PD   0
#define SM_FR   (2 * DSTATES)
#define SM_PN   (SM_FR + 2 * CC)
#define SM_REDD (SM_PN + 2 * NSTATES)
#define SM_REDN (SM_REDD + 24)
#define SM_BC   (SM_REDN + 24)
#define SM_FLOATS (SM_BC + 2)
#define SMEM_FWD_BYTES (SM_FLOATS * 4)

__global__ void __launch_bounds__(FWD_THREADS, 1) __cluster_dims__(CLUSTER, 1, 1)
k_forward(const float* __restrict__ llhs, const int* __restrict__ seqlen,
          const float* __restrict__ den_start, const float* __restrict__ den_final,
          const float* __restrict__ num_start, const float* __restrict__ num_final) {
    extern __shared__ float sm[];
    float* pd   = sm + SM_PD;
    float* fr   = sm + SM_FR;
    float* pn   = sm + SM_PN;
    float* redd = sm + SM_REDD;
    float* redn = sm + SM_REDN;
    float* bc   = sm + SM_BC;

    cg::cluster_group cl = cg::this_cluster();
    unsigned rank = cl.block_rank();
    int pair = blockIdx.x >> 2;       // 0..31 : s*BB + b
    int s = pair >> 4, b = pair & 15;
    const float* llh = llhs + (size_t)pair * TT * CC;
    int Tb = seqlen[b];
    int tid = threadIdx.x;
    int lane = tid & 31, wid = tid >> 5;
    int gb = (int)rank * BB + b;      // valid for rank < 2 (graph index = rank)

    // init den alpha (replicated locally — every CTA computes the full vector)
    for (int i = tid; i < DSTATES; i += FWD_THREADS) pd[i] = __expf(den_start[i]);
    // init num alpha (ranks 0,1)
    if (rank < 2) {
        for (int i = tid; i < NSTATES; i += FWD_THREADS)
            pn[i] = __expf(num_start[gb * NSTATES + i]);
    }
    // stage frame 0: each rank exps its 750-class slice, pushes to all 4 ranks
    if (tid < SLICE) {
        int c = (int)rank * SLICE + tid;
        float v = __expf(llh[c]);
        #pragma unroll
        for (int r = 0; r < CLUSTER; ++r) *(cl.map_shared_rank(&fr[c], r)) = v;
    }
    // row pointers
    int myst = (int)rank * SLICE + tid;
    int dbeg = 0, dend = 0;
    if (tid < SLICE) { dbeg = g_den_rowptr[myst]; dend = g_den_rowptr[myst + 1]; }
    int nbeg = 0, nend = 0;
    if (rank < 2 && tid < NSTATES) { nbeg = g_num_rowptr[gb][tid]; nend = g_num_rowptr[gb][tid + 1]; }

    cl.sync();

    int cur = 0, curn = 0;
    int Ed = 0, En = 0;
    const uint2* __restrict__ darcs = g_den_arcs;
    const uint2* __restrict__ narcs = g_num_arcs + gb * NARCS;

    for (int t = 0; t < Tb; ++t) {
        // ---- pipeline: stage frame t+1 into fr[(t+1)&1] on all ranks ----
        if (t + 1 < Tb && tid < SLICE) {
            int c = (int)rank * SLICE + tid;
            float v = __expf(llh[(size_t)(t + 1) * CC + c]);
            int off = ((t + 1) & 1) * CC + c;
            #pragma unroll
            for (int r = 0; r < CLUSTER; ++r) *(cl.map_shared_rank(&fr[off], r)) = v;
        }

        // ---- joint block-max of current den p (full) and num p ----
        const float* pdc = pd + cur * DSTATES;
        float vd = 0.f, vn = 0.f;
        for (int i = tid; i < DSTATES; i += FWD_THREADS) vd = fmaxf(vd, pdc[i]);
        if (rank < 2 && tid < NSTATES) vn = pn[curn * NSTATES + tid];
        #pragma unroll
        for (int o = 16; o; o >>= 1) {
            vd = fmaxf(vd, __shfl_xor_sync(0xffffffffu, vd, o));
            vn = fmaxf(vn, __shfl_xor_sync(0xffffffffu, vn, o));
        }
        if (lane == 0) { redd[wid] = vd; redn[wid] = vn; }
        __syncthreads();
        if (tid < 32) {
            float md = (tid < FWD_THREADS / 32) ? redd[tid] : 0.f;
            float mn = (tid < FWD_THREADS / 32) ? redn[tid] : 0.f;
            #pragma unroll
            for (int o = 16; o; o >>= 1) {
                md = fmaxf(md, __shfl_xor_sync(0xffffffffu, md, o));
                mn = fmaxf(mn, __shfl_xor_sync(0xffffffffu, mn, o));
            }
            if (tid == 0) { bc[0] = md; bc[1] = mn; }
        }
        __syncthreads();
        float md = bc[0], mn = bc[1];
        int ed = (md > 0.f) ? ((int)(__float_as_uint(md) >> 23) - 127) : 0;
        int en = (mn > 0.f) ? ((int)(__float_as_uint(mn) >> 23) - 127) : 0;
        float invd = __uint_as_float((unsigned)(127 - ed) << 23);  // 2^{-ed}
        float invn = __uint_as_float((unsigned)(127 - en) << 23);
        Ed += ed; En += en;

        // ---- denominator arc loop (pull by dst row), push result to all ranks ----
        const float* frc = fr + (t & 1) * CC;
        int nxt = cur ^ 1;
        if (tid < SLICE) {
            float acc0 = 0.f, acc1 = 0.f;
            int i = dbeg;
            for (; i + 1 < dend; i += 2) {
                uint2 a0 = __ldg(&darcs[i]);
                uint2 a1 = __ldg(&darcs[i + 1]);
                acc0 = fmaf(pdc[a0.x & 0xffffu] * frc[a0.x >> 16], __uint_as_float(a0.y), acc0);
                acc1 = fmaf(pdc[a1.x & 0xffffu] * frc[a1.x >> 16], __uint_as_float(a1.y), acc1);
            }
            if (i < dend) {
                uint2 a0 = __ldg(&darcs[i]);
                acc0 = fmaf(pdc[a0.x & 0xffffu] * frc[a0.x >> 16], __uint_as_float(a0.y), acc0);
            }
            float outv = (acc0 + acc1) * invd;
            int off = nxt * DSTATES + myst;
            #pragma unroll
            for (int r = 0; r < CLUSTER; ++r) *(cl.map_shared_rank(&pd[off], r)) = outv;
        }

        // ---- numerator arc loop (ranks 0,1; graph = rank) ----
        if (rank < 2 && tid < NSTATES) {
            const float* pnc = pn + curn * NSTATES;
            float a = 0.f;
            for (int i = nbeg; i < nend; ++i) {
                uint2 aa = __ldg(&narcs[i]);
                a = fmaf(pnc[aa.x & 0xffffu] * frc[aa.x >> 16], __uint_as_float(aa.y), a);
            }
            pn[(curn ^ 1) * NSTATES + tid] = a * invn;
        }

        cur = nxt; curn ^= 1;
        cl.sync();
    }

    // ---- finals: logZ = E*ln2 + log(sum p * exp(final)) ----
    const float* pdf = pd + cur * DSTATES;
    float sd = 0.f, sn = 0.f;
    for (int i = tid; i < DSTATES; i += FWD_THREADS) sd += pdf[i] * __expf(den_final[i]);
    if (rank < 2 && tid < NSTATES)
        sn = pn[curn * NSTATES + tid] * __expf(num_final[gb * NSTATES + tid]);
    #pragma unroll
    for (int o = 16; o; o >>= 1) {
        sd += __shfl_xor_sync(0xffffffffu, sd, o);
        sn += __shfl_xor_sync(0xffffffffu, sn, o);
    }
    if (lane == 0) { redd[wid] = sd; redn[wid] = sn; }
    __syncthreads();
    if (tid == 0) {
        float totd = 0.f, totn = 0.f;
        for (int w = 0; w < FWD_THREADS / 32; ++w) { totd += redd[w]; totn += redn[w]; }
        if (rank == 0)
            g_denZ[pair] = (totd > 0.f)
                ? (float)((double)Ed * LN2 + log((double)totd)) : -1e30f;
        if (rank < 2)
            g_numZ[s][rank][b] = (totn > 0.f)
                ? (float)((double)En * LN2 + log((double)totn)) : -1e30f;
    }
}

// ---------------- finalize: best permutation + loss sum ----------------
__global__ void k_finalize(float* __restrict__ out) {
    int b = threadIdx.x;  // 32 threads, 16 active
    float loss = 0.f;
    if (b < BB) {
        float p0 = g_numZ[0][0][b] + g_numZ[1][1][b];  // perm (0,1)
        float p1 = g_numZ[0][1][b] + g_numZ[1][0][b];  // perm (1,0)
        float n0, n1;
        if (p1 > p0) { n0 = g_numZ[0][1][b]; n1 = g_numZ[1][0][b]; }
        else         { n0 = g_numZ[0][0][b]; n1 = g_numZ[1][1][b]; }
        loss = -(n0 - g_denZ[b]) - (n1 - g_denZ[BB + b]);
    }
    #pragma unroll
    for (int o = 16; o; o >>= 1) loss += __shfl_xor_sync(0xffffffffu, loss, o);
    if (b == 0) out[0] = loss;
}

// ---------------- launch ----------------
extern "C" void kernel_launch(void* const* d_in, const int* in_sizes, int n_in,
                              void* d_out, int out_size) {
    const float* est    = (const float*)d_in[0];
    const int*   seqlen = (const int*)  d_in[1];
    const int*   nsrc   = (const int*)  d_in[2];
    const int*   ndst   = (const int*)  d_in[3];
    const int*   nlab   = (const int*)  d_in[4];
    const float* nw     = (const float*)d_in[5];
    const float* nst    = (const float*)d_in[6];
    const float* nfi    = (const float*)d_in[7];
    const int*   dsrc   = (const int*)  d_in[8];
    const int*   ddst   = (const int*)  d_in[9];
    const int*   dlab   = (const int*)  d_in[10];
    const float* dw     = (const float*)d_in[11];
    const float* dst0   = (const float*)d_in[12];
    const float* dfin   = (const float*)d_in[13];
    float* out = (float*)d_out;

    k_zero_hist  <<<(DSTATES + 255) / 256, 256>>>();
    k_den_hist   <<<(DARCS + 255) / 256, 256>>>(ddst);
    k_den_scan   <<<1, 1024>>>();
    k_den_scatter<<<(DARCS + 255) / 256, 256>>>(dsrc, ddst, dlab, dw);
    k_num_prep   <<<NPAIR, 512>>>(nsrc, ndst, nlab, nw);

    cudaFuncSetAttribute(k_forward, cudaFuncAttributeMaxDynamicSharedMemorySize,
                         SMEM_FWD_BYTES);
    k_forward<<<NPAIR * CLUSTER, FWD_THREADS, SMEM_FWD_BYTES>>>(
        est, seqlen, dst0, dfin, nst, nfi);

    k_finalize<<<1, 32>>>(out);
}